// round 4
// baseline (speedup 1.0000x reference)
#include <cuda_runtime.h>

// ---------------- problem constants ----------------
#define D_MODEL  1024
#define D_STATE  16
#define D_CONV   4
#define D_INNER  2048
#define BATCH    2
#define SEQ      2048
#define ROWS     (BATCH*SEQ)          // 4096

// ---------------- scratch (static __device__, no allocs) ----------------
__device__ float g_xz  [ROWS * 2 * D_INNER];   // [4096, 4096]  x_proj | z
__device__ float g_xact[ROWS * D_INNER];       // conv+silu output
__device__ float g_dt  [ROWS * D_INNER];       // softplus(dt)
__device__ float g_yg  [ROWS * D_INNER];       // gated ssm output

// ---------------- f32x2 helpers (Blackwell packed fp32) ----------------
__device__ __forceinline__ unsigned long long pack2(float lo, float hi) {
    unsigned long long r;
    asm("mov.b64 %0, {%1,%2};" : "=l"(r) : "f"(lo), "f"(hi));
    return r;
}
__device__ __forceinline__ float2 unpack2(unsigned long long v) {
    float2 r;
    asm("mov.b64 {%0,%1}, %2;" : "=f"(r.x), "=f"(r.y) : "l"(v));
    return r;
}
__device__ __forceinline__ void ffma2(unsigned long long& d,
                                      unsigned long long a,
                                      unsigned long long b) {
    asm("fma.rn.f32x2 %0, %1, %2, %0;" : "+l"(d) : "l"(a), "l"(b));
}

__device__ __forceinline__ float softplus_f(float v) {
    return fmaxf(v, 0.0f) + log1pf(__expf(-fabsf(v)));
}

// ---------------- GEMM: C[M,N] = A[M,K] * B[N,K]^T  (both row-major) ----------------
// 128x128 block tile, BK=16, 256 threads, 8x8 per-thread tile, f32x2 FMAs.
// 2-stage smem double buffer with register prefetch: global loads for tile kt+1
// are issued BEFORE the 16-k compute loop on tile kt, stores to the alternate
// stage happen after, one __syncthreads per tile.
// epi = 0: plain store;  epi = 1: softplus(v + bias[n])
__global__ void __launch_bounds__(256, 2)
gemm_tn(const float* __restrict__ A, const float* __restrict__ B,
        float* __restrict__ C, int M, int N, int K,
        const float* __restrict__ bias, int epi)
{
    __shared__ __align__(16) float As[2][16][128];
    __shared__ __align__(16) float Bs[2][16][128];

    const int tid = threadIdx.x;
    const int m0  = blockIdx.y * 128;
    const int n0  = blockIdx.x * 128;
    const int tx  = tid & 15;          // 0..15 -> col group
    const int ty  = tid >> 4;          // 0..15 -> row group
    const int r0  = ty * 8;
    const int c0  = tx * 8;

    // global-load mapping: 512 float4 per tile side, 2 per thread
    const int q0r = tid >> 2;          // row within tile for f4 #0 (0..63)
    const int q0c = tid & 3;           // which float4 within the 16-wide k row
    const int q1r = q0r + 64;          // row for f4 #1
    const int kk  = q0c * 4;           // k offset of this thread's float4

    const float* pA0 = A + (size_t)(m0 + q0r) * K + kk;
    const float* pA1 = A + (size_t)(m0 + q1r) * K + kk;
    const float* pB0 = B + (size_t)(n0 + q0r) * K + kk;
    const float* pB1 = B + (size_t)(n0 + q1r) * K + kk;

    unsigned long long acc[8][4];
#pragma unroll
    for (int i = 0; i < 8; i++)
#pragma unroll
        for (int j = 0; j < 4; j++) acc[i][j] = 0ULL;

    const int ktiles = K >> 4;

    // ---- prologue: load tile 0 and stage it ----
    float4 v0 = *(const float4*)(pA0);
    float4 v1 = *(const float4*)(pA1);
    float4 w0 = *(const float4*)(pB0);
    float4 w1 = *(const float4*)(pB1);
    {
        As[0][kk + 0][q0r] = v0.x; As[0][kk + 1][q0r] = v0.y;
        As[0][kk + 2][q0r] = v0.z; As[0][kk + 3][q0r] = v0.w;
        As[0][kk + 0][q1r] = v1.x; As[0][kk + 1][q1r] = v1.y;
        As[0][kk + 2][q1r] = v1.z; As[0][kk + 3][q1r] = v1.w;
        Bs[0][kk + 0][q0r] = w0.x; Bs[0][kk + 1][q0r] = w0.y;
        Bs[0][kk + 2][q0r] = w0.z; Bs[0][kk + 3][q0r] = w0.w;
        Bs[0][kk + 0][q1r] = w1.x; Bs[0][kk + 1][q1r] = w1.y;
        Bs[0][kk + 2][q1r] = w1.z; Bs[0][kk + 3][q1r] = w1.w;
    }
    __syncthreads();

    for (int kt = 0; kt < ktiles; kt++) {
        const int cur = kt & 1;
        const int nxt = cur ^ 1;
        const bool more = (kt + 1) < ktiles;

        // issue next tile's global loads FIRST (latency hidden by compute)
        if (more) {
            const int kb = (kt + 1) << 4;
            v0 = *(const float4*)(pA0 + kb);
            v1 = *(const float4*)(pA1 + kb);
            w0 = *(const float4*)(pB0 + kb);
            w1 = *(const float4*)(pB1 + kb);
        }

        // compute on current stage
#pragma unroll
        for (int k = 0; k < 16; k++) {
            float a[8];
            *(float4*)&a[0] = *(const float4*)&As[cur][k][r0];
            *(float4*)&a[4] = *(const float4*)&As[cur][k][r0 + 4];
            unsigned long long b2[4];
            {
                ulonglong2 t0 = *(const ulonglong2*)&Bs[cur][k][c0];
                ulonglong2 t1 = *(const ulonglong2*)&Bs[cur][k][c0 + 4];
                b2[0] = t0.x; b2[1] = t0.y; b2[2] = t1.x; b2[3] = t1.y;
            }
#pragma unroll
            for (int i = 0; i < 8; i++) {
                unsigned long long aa = pack2(a[i], a[i]);
#pragma unroll
                for (int j = 0; j < 4; j++) ffma2(acc[i][j], aa, b2[j]);
            }
        }

        // stage next tile into the other buffer (prev compute on it finished
        // at the barrier ending iteration kt-1)
        if (more) {
            As[nxt][kk + 0][q0r] = v0.x; As[nxt][kk + 1][q0r] = v0.y;
            As[nxt][kk + 2][q0r] = v0.z; As[nxt][kk + 3][q0r] = v0.w;
            As[nxt][kk + 0][q1r] = v1.x; As[nxt][kk + 1][q1r] = v1.y;
            As[nxt][kk + 2][q1r] = v1.z; As[nxt][kk + 3][q1r] = v1.w;
            Bs[nxt][kk + 0][q0r] = w0.x; Bs[nxt][kk + 1][q0r] = w0.y;
            Bs[nxt][kk + 2][q0r] = w0.z; Bs[nxt][kk + 3][q0r] = w0.w;
            Bs[nxt][kk + 0][q1r] = w1.x; Bs[nxt][kk + 1][q1r] = w1.y;
            Bs[nxt][kk + 2][q1r] = w1.z; Bs[nxt][kk + 3][q1r] = w1.w;
        }
        __syncthreads();
    }

    // epilogue
#pragma unroll
    for (int i = 0; i < 8; i++) {
        const int m = m0 + r0 + i;
#pragma unroll
        for (int j = 0; j < 4; j++) {
            const int n = n0 + c0 + 2 * j;
            float2 v = unpack2(acc[i][j]);
            if (epi == 1) {
                v.x = softplus_f(v.x + bias[n]);
                v.y = softplus_f(v.y + bias[n + 1]);
            }
            *(float2*)(C + (size_t)m * N + n) = v;
        }
    }
}

// ---------------- depthwise causal conv1d + SiLU ----------------
__global__ void conv_silu_kernel(const float* __restrict__ conv_w,
                                 const float* __restrict__ conv_b)
{
    int idx = blockIdx.x * blockDim.x + threadIdx.x;    // over ROWS*D_INNER
    if (idx >= ROWS * D_INNER) return;
    int d   = idx & (D_INNER - 1);
    int row = idx >> 11;                 // / D_INNER
    int t   = row & (SEQ - 1);
    int b   = row >> 11;                 // / SEQ

    float acc = conv_b[d];
#pragma unroll
    for (int j = 0; j < D_CONV; j++) {
        int tt = t - (D_CONV - 1) + j;
        if (tt >= 0)
            acc = fmaf(conv_w[d * D_CONV + j],
                       g_xz[(size_t)(b * SEQ + tt) * (2 * D_INNER) + d], acc);
    }
    float sig = 1.0f / (1.0f + __expf(-acc));
    g_xact[idx] = acc * sig;
}

// ---------------- selective scan + gating ----------------
// one thread per (b, d, s): 65536 threads; lanes [16k..16k+15] share a channel
__global__ void __launch_bounds__(256)
scan_kernel(const float* __restrict__ A_log, const float* __restrict__ Dp)
{
    int g   = blockIdx.x * blockDim.x + threadIdx.x;
    int s   = g & (D_STATE - 1);
    int dch = g >> 4;                    // b*D_INNER + d
    int b   = dch >> 11;                 // / D_INNER
    int d   = dch & (D_INNER - 1);

    const float a   = -__expf(A_log[d * D_STATE + s]);
    const float dpv = Dp[d];

    const float* dt_ptr = g_dt   + (size_t)(b * SEQ) * D_INNER + d;
    const float* x_ptr  = g_xact + (size_t)(b * SEQ) * D_INNER + d;
    const float* z_ptr  = g_xz   + (size_t)(b * SEQ) * (2 * D_INNER) + D_INNER + d;
    float*       y_ptr  = g_yg   + (size_t)(b * SEQ) * D_INNER + d;

    float h = 0.0f;
#pragma unroll 4
    for (int t = 0; t < SEQ; t++) {
        float dtv = dt_ptr[(size_t)t * D_INNER];
        float xv  = x_ptr [(size_t)t * D_INNER];
        float e   = __expf(dtv * a);
        h = fmaf(e, h, dtv * xv);

        float y = h;
        y += __shfl_xor_sync(0xffffffffu, y, 1);
        y += __shfl_xor_sync(0xffffffffu, y, 2);
        y += __shfl_xor_sync(0xffffffffu, y, 4);
        y += __shfl_xor_sync(0xffffffffu, y, 8);

        if (s == 0) {
            float zv  = z_ptr[(size_t)t * (2 * D_INNER)];
            float sig = 1.0f / (1.0f + __expf(-zv));
            y_ptr[(size_t)t * D_INNER] = (y + dpv * xv) * (zv * sig);
        }
    }
}

// ---------------- launch ----------------
extern "C" void kernel_launch(void* const* d_in, const int* in_sizes, int n_in,
                              void* d_out, int out_size)
{
    const float* x      = (const float*)d_in[0];
    const float* W_in   = (const float*)d_in[1];
    const float* conv_w = (const float*)d_in[2];
    const float* conv_b = (const float*)d_in[3];
    const float* A_log  = (const float*)d_in[4];
    const float* Dp     = (const float*)d_in[5];
    const float* W_dt   = (const float*)d_in[6];
    const float* b_dt   = (const float*)d_in[7];
    const float* W_out  = (const float*)d_in[8];
    float* out = (float*)d_out;

    float *p_xz, *p_xact, *p_dt, *p_yg;
    cudaGetSymbolAddress((void**)&p_xz,   g_xz);
    cudaGetSymbolAddress((void**)&p_xact, g_xact);
    cudaGetSymbolAddress((void**)&p_dt,   g_dt);
    cudaGetSymbolAddress((void**)&p_yg,   g_yg);

    // G1: xz = x @ W_in^T    [4096,1024] x [4096,1024]^T -> [4096,4096]
    gemm_tn<<<dim3((2 * D_INNER) / 128, ROWS / 128), 256>>>(
        x, W_in, p_xz, ROWS, 2 * D_INNER, D_MODEL, nullptr, 0);

    // conv + silu -> g_xact
    conv_silu_kernel<<<(ROWS * D_INNER) / 256, 256>>>(conv_w, conv_b);

    // G2: dt = softplus(x_act @ W_dt^T + b_dt)  [4096,2048]x[2048,2048]^T
    gemm_tn<<<dim3(D_INNER / 128, ROWS / 128), 256>>>(
        p_xact, W_dt, p_dt, ROWS, D_INNER, D_INNER, b_dt, 1);

    // scan + gating -> g_yg   (BATCH*D_INNER*D_STATE = 65536 threads)
    scan_kernel<<<(BATCH * D_INNER * D_STATE) / 256, 256>>>(A_log, Dp);

    // G3: out = y_gated @ W_out^T -> d_out [4096, 1024]
    gemm_tn<<<dim3(D_MODEL / 128, ROWS / 128), 256>>>(
        p_yg, W_out, out, ROWS, D_MODEL, D_INNER, nullptr, 0);
}

// round 7
// speedup vs baseline: 1.3790x; 1.3790x over previous
#include <cuda_runtime.h>
#include <cuda_bf16.h>
#include <cstdint>

// ---------------- problem constants ----------------
#define D_MODEL  1024
#define D_STATE  16
#define D_CONV   4
#define D_INNER  2048
#define BATCH    2
#define SEQ      2048
#define ROWS     (BATCH*SEQ)          // 4096

// ---------------- scratch (static __device__, no allocs) ----------------
__device__ float g_xz[ROWS * 2 * D_INNER];   // [4096,4096] x_proj | z (fp32)
__device__ float g_dt[ROWS * D_INNER];       // softplus(dt) (fp32)

// bf16 split operands (hi/lo)
__device__ __nv_bfloat16 g_xh [ROWS * D_MODEL],        g_xl [ROWS * D_MODEL];
__device__ __nv_bfloat16 g_wih[2 * D_INNER * D_MODEL], g_wil[2 * D_INNER * D_MODEL];
__device__ __nv_bfloat16 g_wdh[D_INNER * D_INNER],     g_wdl[D_INNER * D_INNER];
__device__ __nv_bfloat16 g_woh[D_MODEL * D_INNER],     g_wol[D_MODEL * D_INNER];
__device__ __nv_bfloat16 g_xah[ROWS * D_INNER],        g_xal[ROWS * D_INNER];
__device__ __nv_bfloat16 g_ygh[ROWS * D_INNER],        g_ygl[ROWS * D_INNER];

// ---------------- PTX helpers (baseline ISA only — no 'a' features) ----------------
__device__ __forceinline__ uint32_t smem_u32(const void* p) {
    uint32_t a;
    asm("{ .reg .u64 t; cvta.to.shared.u64 t, %1; cvt.u32.u64 %0, t; }" : "=r"(a) : "l"(p));
    return a;
}
__device__ __forceinline__ void cp16(uint32_t dst, const void* src) {
    asm volatile("cp.async.cg.shared.global [%0], [%1], 16;" :: "r"(dst), "l"(src));
}
__device__ __forceinline__ void cp_commit() {
    asm volatile("cp.async.commit_group;" ::: "memory");
}
__device__ __forceinline__ void ldsm4(uint32_t* r, uint32_t addr) {
    asm volatile("ldmatrix.sync.aligned.m8n8.x4.shared.b16 {%0,%1,%2,%3}, [%4];"
                 : "=r"(r[0]), "=r"(r[1]), "=r"(r[2]), "=r"(r[3]) : "r"(addr));
}
__device__ __forceinline__ void mma16816(float* c, const uint32_t* a, const uint32_t* b) {
    asm volatile("mma.sync.aligned.m16n8k16.row.col.f32.bf16.bf16.f32 "
                 "{%0,%1,%2,%3}, {%4,%5,%6,%7}, {%8,%9}, {%0,%1,%2,%3};"
                 : "+f"(c[0]), "+f"(c[1]), "+f"(c[2]), "+f"(c[3])
                 : "r"(a[0]), "r"(a[1]), "r"(a[2]), "r"(a[3]), "r"(b[0]), "r"(b[1]));
}

__device__ __forceinline__ float softplus_f(float v) {
    return fmaxf(v, 0.0f) + log1pf(__expf(-fabsf(v)));
}

// ---------------- split kernel: v -> bf16 hi + bf16 lo ----------------
__global__ void split_kernel(const float* __restrict__ in,
                             __nv_bfloat16* __restrict__ hi,
                             __nv_bfloat16* __restrict__ lo, int n)
{
    int i = (blockIdx.x * blockDim.x + threadIdx.x) * 4;
    if (i >= n) return;
    float4 v = *(const float4*)(in + i);
    __nv_bfloat16 h0 = __float2bfloat16_rn(v.x);
    __nv_bfloat16 h1 = __float2bfloat16_rn(v.y);
    __nv_bfloat16 h2 = __float2bfloat16_rn(v.z);
    __nv_bfloat16 h3 = __float2bfloat16_rn(v.w);
    __nv_bfloat162 hp0; hp0.x = h0; hp0.y = h1;
    __nv_bfloat162 hp1; hp1.x = h2; hp1.y = h3;
    __nv_bfloat162 lp0, lp1;
    lp0.x = __float2bfloat16_rn(v.x - __bfloat162float(h0));
    lp0.y = __float2bfloat16_rn(v.y - __bfloat162float(h1));
    lp1.x = __float2bfloat16_rn(v.z - __bfloat162float(h2));
    lp1.y = __float2bfloat16_rn(v.w - __bfloat162float(h3));
    *(__nv_bfloat162*)(hi + i)     = hp0;
    *(__nv_bfloat162*)(hi + i + 2) = hp1;
    *(__nv_bfloat162*)(lo + i)     = lp0;
    *(__nv_bfloat162*)(lo + i + 2) = lp1;
}

// ---------------- warp-MMA GEMM: C[M,N] = (Ah+Al)[M,K] @ (Bh+Bl)[N,K]^T ----------------
// 128x128 CTA tile, BK=32, 8 warps (2x4 -> 64x32 per warp), bf16x3 products into
// shared fp32 accumulators. 2-stage cp.async pipeline.
// smem: per stage 4 tiles (Ah,Al,Bh,Bl) of [128 rows x 32 bf16], row pitch 80B
// (16B x 5 -> conflict-free ldmatrix). Tile = 10240B; stage = 40960B; 2 stages.
#define TILE_BYTES   10240
#define STAGE_BYTES  40960
#define GEMM_SMEM    (2 * STAGE_BYTES)

__global__ void __launch_bounds__(256)
gemm_bf16mma(const __nv_bfloat16* __restrict__ Ah, const __nv_bfloat16* __restrict__ Al,
             const __nv_bfloat16* __restrict__ Bh, const __nv_bfloat16* __restrict__ Bl,
             float* __restrict__ C, int M, int N, int K,
             const float* __restrict__ bias, int epi)
{
    extern __shared__ __align__(128) char smem[];
    const uint32_t sbase = smem_u32(smem);
    const int tid  = threadIdx.x;
    const int lane = tid & 31;
    const int wid  = tid >> 5;
    const int warp_m = wid & 1;        // 2 x 64 rows
    const int warp_n = wid >> 1;       // 4 x 32 cols
    const int m0 = blockIdx.y * 128;
    const int n0 = blockIdx.x * 128;

    // ---- per-thread cp.async mapping: 8 chunks of 16B per stage ----
    const __nv_bfloat16* gsrc[8];
    uint32_t sdst[8];
#pragma unroll
    for (int i = 0; i < 8; i++) {
        int idx  = tid + 256 * i;      // 0..2047
        int tile = idx >> 9;           // 0:Ah 1:Al 2:Bh 3:Bl
        int w    = idx & 511;
        int row  = w >> 2;             // 0..127
        int c    = w & 3;              // 16B chunk in row
        const __nv_bfloat16* base =
            (tile == 0) ? Ah : (tile == 1) ? Al : (tile == 2) ? Bh : Bl;
        int grow = (tile < 2) ? (m0 + row) : (n0 + row);
        gsrc[i] = base + (size_t)grow * K + c * 8;
        sdst[i] = (uint32_t)(tile * TILE_BYTES + row * 80 + c * 16);
    }

    // ---- ldmatrix lane->address offsets ----
    const int rowA = lane & 15;
    const int colA = ((lane >> 4) & 1) * 16;
    const uint32_t offA = (uint32_t)((warp_m * 64 + rowA) * 80 + colA);
    const int rowB = ((lane >> 4) & 1) * 8 + (lane & 7);
    const int colB = ((lane >> 3) & 1) * 16;
    const uint32_t offB = (uint32_t)((warp_n * 32 + rowB) * 80 + colB);

    float acc[4][4][4];
#pragma unroll
    for (int i = 0; i < 4; i++)
#pragma unroll
        for (int j = 0; j < 4; j++)
#pragma unroll
            for (int q = 0; q < 4; q++) acc[i][j][q] = 0.0f;

    const int nk = K >> 5;             // K/32 chunks

    // ---- prologue: stage 0 ----
    {
        const uint32_t sb = sbase;
#pragma unroll
        for (int i = 0; i < 8; i++) cp16(sb + sdst[i], gsrc[i]);
        cp_commit();
    }

    for (int kt = 0; kt < nk; kt++) {
        const int cur = kt & 1;
        if (kt + 1 < nk) {
            const uint32_t sb = sbase + (cur ^ 1) * STAGE_BYTES;
            const int kofs = (kt + 1) << 5;
#pragma unroll
            for (int i = 0; i < 8; i++) cp16(sb + sdst[i], gsrc[i] + kofs);
            cp_commit();
            asm volatile("cp.async.wait_group 1;" ::: "memory");
        } else {
            asm volatile("cp.async.wait_group 0;" ::: "memory");
        }
        __syncthreads();

        const uint32_t sb = sbase + cur * STAGE_BYTES;
#pragma unroll
        for (int ks = 0; ks < 2; ks++) {
            uint32_t aH[4][4], aL[4][4], bH[4][2], bL[4][2], t4[4];
#pragma unroll
            for (int i = 0; i < 4; i++) {
                ldsm4(aH[i], sb + 0 * TILE_BYTES + offA + i * 1280 + ks * 32);
                ldsm4(aL[i], sb + 1 * TILE_BYTES + offA + i * 1280 + ks * 32);
            }
            ldsm4(t4, sb + 2 * TILE_BYTES + offB + 0 * 1280 + ks * 32);
            bH[0][0] = t4[0]; bH[0][1] = t4[1]; bH[1][0] = t4[2]; bH[1][1] = t4[3];
            ldsm4(t4, sb + 2 * TILE_BYTES + offB + 1 * 1280 + ks * 32);
            bH[2][0] = t4[0]; bH[2][1] = t4[1]; bH[3][0] = t4[2]; bH[3][1] = t4[3];
            ldsm4(t4, sb + 3 * TILE_BYTES + offB + 0 * 1280 + ks * 32);
            bL[0][0] = t4[0]; bL[0][1] = t4[1]; bL[1][0] = t4[2]; bL[1][1] = t4[3];
            ldsm4(t4, sb + 3 * TILE_BYTES + offB + 1 * 1280 + ks * 32);
            bL[2][0] = t4[0]; bL[2][1] = t4[1]; bL[3][0] = t4[2]; bL[3][1] = t4[3];

#pragma unroll
            for (int i = 0; i < 4; i++)
#pragma unroll
                for (int j = 0; j < 4; j++) {
                    mma16816(acc[i][j], aH[i], bH[j]);
                    mma16816(acc[i][j], aH[i], bL[j]);
                    mma16816(acc[i][j], aL[i], bH[j]);
                }
        }
        __syncthreads();
    }

    // ---- epilogue: registers -> gmem ----
#pragma unroll
    for (int i = 0; i < 4; i++) {
        const int m = m0 + warp_m * 64 + i * 16 + (lane >> 2);
#pragma unroll
        for (int j = 0; j < 4; j++) {
            const int n = n0 + warp_n * 32 + j * 8 + (lane & 3) * 2;
            float c0 = acc[i][j][0], c1 = acc[i][j][1];
            float c2 = acc[i][j][2], c3 = acc[i][j][3];
            if (epi == 1) {
                const float b0 = bias[n], b1 = bias[n + 1];
                c0 = softplus_f(c0 + b0); c1 = softplus_f(c1 + b1);
                c2 = softplus_f(c2 + b0); c3 = softplus_f(c3 + b1);
            }
            float2 v01; v01.x = c0; v01.y = c1;
            float2 v23; v23.x = c2; v23.y = c3;
            *(float2*)(C + (size_t)m * N + n)       = v01;
            *(float2*)(C + (size_t)(m + 8) * N + n) = v23;
        }
    }
}

// ---------------- depthwise causal conv1d + SiLU -> bf16 split ----------------
__global__ void conv_silu_kernel(const float* __restrict__ conv_w,
                                 const float* __restrict__ conv_b)
{
    int idx = blockIdx.x * blockDim.x + threadIdx.x;    // over ROWS*D_INNER
    if (idx >= ROWS * D_INNER) return;
    int d   = idx & (D_INNER - 1);
    int row = idx >> 11;                 // / D_INNER
    int t   = row & (SEQ - 1);
    int b   = row >> 11;                 // / SEQ

    float acc = conv_b[d];
#pragma unroll
    for (int j = 0; j < D_CONV; j++) {
        int tt = t - (D_CONV - 1) + j;
        if (tt >= 0)
            acc = fmaf(conv_w[d * D_CONV + j],
                       g_xz[(size_t)(b * SEQ + tt) * (2 * D_INNER) + d], acc);
    }
    float sig = 1.0f / (1.0f + __expf(-acc));
    float v = acc * sig;
    __nv_bfloat16 h = __float2bfloat16_rn(v);
    g_xah[idx] = h;
    g_xal[idx] = __float2bfloat16_rn(v - __bfloat162float(h));
}

// ---------------- selective scan + gating -> bf16 split ----------------
__global__ void __launch_bounds__(256)
scan_kernel(const float* __restrict__ A_log, const float* __restrict__ Dp)
{
    int g   = blockIdx.x * blockDim.x + threadIdx.x;
    int s   = g & (D_STATE - 1);
    int dch = g >> 4;                    // b*D_INNER + d
    int b   = dch >> 11;                 // / D_INNER
    int d   = dch & (D_INNER - 1);

    const float a   = -__expf(A_log[d * D_STATE + s]);
    const float dpv = Dp[d];

    const float* dt_ptr = g_dt + (size_t)(b * SEQ) * D_INNER + d;
    const __nv_bfloat16* xh_ptr = g_xah + (size_t)(b * SEQ) * D_INNER + d;
    const __nv_bfloat16* xl_ptr = g_xal + (size_t)(b * SEQ) * D_INNER + d;
    const float* z_ptr  = g_xz + (size_t)(b * SEQ) * (2 * D_INNER) + D_INNER + d;
    __nv_bfloat16* yh_ptr = g_ygh + (size_t)(b * SEQ) * D_INNER + d;
    __nv_bfloat16* yl_ptr = g_ygl + (size_t)(b * SEQ) * D_INNER + d;

    float h = 0.0f;
#pragma unroll 4
    for (int t = 0; t < SEQ; t++) {
        float dtv = dt_ptr[(size_t)t * D_INNER];
        float xv  = __bfloat162float(xh_ptr[(size_t)t * D_INNER]) +
                    __bfloat162float(xl_ptr[(size_t)t * D_INNER]);
        float e   = __expf(dtv * a);
        h = fmaf(e, h, dtv * xv);

        float y = h;
        y += __shfl_xor_sync(0xffffffffu, y, 1);
        y += __shfl_xor_sync(0xffffffffu, y, 2);
        y += __shfl_xor_sync(0xffffffffu, y, 4);
        y += __shfl_xor_sync(0xffffffffu, y, 8);

        if (s == 0) {
            float zv  = z_ptr[(size_t)t * (2 * D_INNER)];
            float sig = 1.0f / (1.0f + __expf(-zv));
            float yg  = (y + dpv * xv) * (zv * sig);
            __nv_bfloat16 hh = __float2bfloat16_rn(yg);
            yh_ptr[(size_t)t * D_INNER] = hh;
            yl_ptr[(size_t)t * D_INNER] = __float2bfloat16_rn(yg - __bfloat162float(hh));
        }
    }
}

// ---------------- launch ----------------
extern "C" void kernel_launch(void* const* d_in, const int* in_sizes, int n_in,
                              void* d_out, int out_size)
{
    const float* x      = (const float*)d_in[0];
    const float* W_in   = (const float*)d_in[1];
    const float* conv_w = (const float*)d_in[2];
    const float* conv_b = (const float*)d_in[3];
    const float* A_log  = (const float*)d_in[4];
    const float* Dp     = (const float*)d_in[5];
    const float* W_dt   = (const float*)d_in[6];
    const float* b_dt   = (const float*)d_in[7];
    const float* W_out  = (const float*)d_in[8];
    float* out = (float*)d_out;

    // allow >48KB dynamic smem (no-op after first call)
    cudaFuncSetAttribute(gemm_bf16mma, cudaFuncAttributeMaxDynamicSharedMemorySize,
                         GEMM_SMEM);

    float *p_xz, *p_dt;
    cudaGetSymbolAddress((void**)&p_xz, g_xz);
    cudaGetSymbolAddress((void**)&p_dt, g_dt);
    __nv_bfloat16 *p_xh, *p_xl, *p_wih, *p_wil, *p_wdh, *p_wdl, *p_woh, *p_wol;
    __nv_bfloat16 *p_xah, *p_xal, *p_ygh, *p_ygl;
    cudaGetSymbolAddress((void**)&p_xh,  g_xh);
    cudaGetSymbolAddress((void**)&p_xl,  g_xl);
    cudaGetSymbolAddress((void**)&p_wih, g_wih);
    cudaGetSymbolAddress((void**)&p_wil, g_wil);
    cudaGetSymbolAddress((void**)&p_wdh, g_wdh);
    cudaGetSymbolAddress((void**)&p_wdl, g_wdl);
    cudaGetSymbolAddress((void**)&p_woh, g_woh);
    cudaGetSymbolAddress((void**)&p_wol, g_wol);
    cudaGetSymbolAddress((void**)&p_xah, g_xah);
    cudaGetSymbolAddress((void**)&p_xal, g_xal);
    cudaGetSymbolAddress((void**)&p_ygh, g_ygh);
    cudaGetSymbolAddress((void**)&p_ygl, g_ygl);

    // splits of inputs/weights
    split_kernel<<<(ROWS * D_MODEL) / 1024, 256>>>(x, p_xh, p_xl, ROWS * D_MODEL);
    split_kernel<<<(2 * D_INNER * D_MODEL) / 1024, 256>>>(W_in, p_wih, p_wil, 2 * D_INNER * D_MODEL);
    split_kernel<<<(D_INNER * D_INNER) / 1024, 256>>>(W_dt, p_wdh, p_wdl, D_INNER * D_INNER);
    split_kernel<<<(D_MODEL * D_INNER) / 1024, 256>>>(W_out, p_woh, p_wol, D_MODEL * D_INNER);

    // G1: xz = x @ W_in^T   [4096,1024] x [4096,1024]^T -> [4096,4096]
    gemm_bf16mma<<<dim3((2 * D_INNER) / 128, ROWS / 128), 256, GEMM_SMEM>>>(
        p_xh, p_xl, p_wih, p_wil, p_xz, ROWS, 2 * D_INNER, D_MODEL, nullptr, 0);

    // conv + silu -> xact (bf16 split)
    conv_silu_kernel<<<(ROWS * D_INNER) / 256, 256>>>(conv_w, conv_b);

    // G2: dt = softplus(xact @ W_dt^T + b_dt)  [4096,2048]x[2048,2048]^T
    gemm_bf16mma<<<dim3(D_INNER / 128, ROWS / 128), 256, GEMM_SMEM>>>(
        p_xah, p_xal, p_wdh, p_wdl, p_dt, ROWS, D_INNER, D_INNER, b_dt, 1);

    // scan + gating -> yg (bf16 split)
    scan_kernel<<<(BATCH * D_INNER * D_STATE) / 256, 256>>>(A_log, Dp);

    // G3: out = yg @ W_out^T -> [4096,1024]
    gemm_bf16mma<<<dim3(D_MODEL / 128, ROWS / 128), 256, GEMM_SMEM>>>(
        p_ygh, p_ygl, p_woh, p_wol, out, ROWS, D_MODEL, D_INNER, nullptr, 0);
}

// round 8
// speedup vs baseline: 1.3823x; 1.0024x over previous
#include <cuda_runtime.h>
#include <cuda_bf16.h>
#include <cstdint>

// ---------------- problem constants ----------------
#define D_MODEL  1024
#define D_STATE  16
#define D_CONV   4
#define D_INNER  2048
#define BATCH    2
#define SEQ      2048
#define ROWS     (BATCH*SEQ)          // 4096

// ---------------- scratch (static __device__, no allocs) ----------------
__device__ float g_xz[ROWS * 2 * D_INNER];   // [4096,4096] x_proj | z (fp32)
__device__ float g_dt[ROWS * D_INNER];       // softplus(dt) (fp32)

// bf16 split operands (hi/lo)
__device__ __nv_bfloat16 g_xh [ROWS * D_MODEL],        g_xl [ROWS * D_MODEL];
__device__ __nv_bfloat16 g_wih[2 * D_INNER * D_MODEL], g_wil[2 * D_INNER * D_MODEL];
__device__ __nv_bfloat16 g_wdh[D_INNER * D_INNER],     g_wdl[D_INNER * D_INNER];
__device__ __nv_bfloat16 g_woh[D_MODEL * D_INNER],     g_wol[D_MODEL * D_INNER];
__device__ __nv_bfloat16 g_xah[ROWS * D_INNER],        g_xal[ROWS * D_INNER];
__device__ __nv_bfloat16 g_ygh[ROWS * D_INNER],        g_ygl[ROWS * D_INNER];

// ---------------- PTX helpers (baseline ISA only — no 'a' features) ----------------
__device__ __forceinline__ uint32_t smem_u32(const void* p) {
    uint32_t a;
    asm("{ .reg .u64 t; cvta.to.shared.u64 t, %1; cvt.u32.u64 %0, t; }" : "=r"(a) : "l"(p));
    return a;
}
__device__ __forceinline__ void cp16(uint32_t dst, const void* src) {
    asm volatile("cp.async.cg.shared.global [%0], [%1], 16;" :: "r"(dst), "l"(src));
}
__device__ __forceinline__ void cp_commit() {
    asm volatile("cp.async.commit_group;" ::: "memory");
}
__device__ __forceinline__ void ldsm4(uint32_t* r, uint32_t addr) {
    asm volatile("ldmatrix.sync.aligned.m8n8.x4.shared.b16 {%0,%1,%2,%3}, [%4];"
                 : "=r"(r[0]), "=r"(r[1]), "=r"(r[2]), "=r"(r[3]) : "r"(addr));
}
__device__ __forceinline__ void mma16816(float* c, const uint32_t* a, const uint32_t* b) {
    asm volatile("mma.sync.aligned.m16n8k16.row.col.f32.bf16.bf16.f32 "
                 "{%0,%1,%2,%3}, {%4,%5,%6,%7}, {%8,%9}, {%0,%1,%2,%3};"
                 : "+f"(c[0]), "+f"(c[1]), "+f"(c[2]), "+f"(c[3])
                 : "r"(a[0]), "r"(a[1]), "r"(a[2]), "r"(a[3]), "r"(b[0]), "r"(b[1]));
}

__device__ __forceinline__ float softplus_f(float v) {
    return fmaxf(v, 0.0f) + log1pf(__expf(-fabsf(v)));
}

// ---------------- split kernel: v -> bf16 hi + bf16 lo ----------------
__global__ void split_kernel(const float* __restrict__ in,
                             __nv_bfloat16* __restrict__ hi,
                             __nv_bfloat16* __restrict__ lo, int n)
{
    int i = (blockIdx.x * blockDim.x + threadIdx.x) * 4;
    if (i >= n) return;
    float4 v = *(const float4*)(in + i);
    __nv_bfloat16 h0 = __float2bfloat16_rn(v.x);
    __nv_bfloat16 h1 = __float2bfloat16_rn(v.y);
    __nv_bfloat16 h2 = __float2bfloat16_rn(v.z);
    __nv_bfloat16 h3 = __float2bfloat16_rn(v.w);
    __nv_bfloat162 hp0; hp0.x = h0; hp0.y = h1;
    __nv_bfloat162 hp1; hp1.x = h2; hp1.y = h3;
    __nv_bfloat162 lp0, lp1;
    lp0.x = __float2bfloat16_rn(v.x - __bfloat162float(h0));
    lp0.y = __float2bfloat16_rn(v.y - __bfloat162float(h1));
    lp1.x = __float2bfloat16_rn(v.z - __bfloat162float(h2));
    lp1.y = __float2bfloat16_rn(v.w - __bfloat162float(h3));
    *(__nv_bfloat162*)(hi + i)     = hp0;
    *(__nv_bfloat162*)(hi + i + 2) = hp1;
    *(__nv_bfloat162*)(lo + i)     = lp0;
    *(__nv_bfloat162*)(lo + i + 2) = lp1;
}

// ---------------- warp-MMA GEMM: C[M,N] = (Ah+Al)[M,K] @ (Bh+Bl)[N,K]^T ----------------
// 128x128 CTA tile, BK=32, 8 warps (2x4 -> 64x32 per warp), bf16x3 products into
// shared fp32 accumulators. 2-stage cp.async pipeline.
// Product-major MMA ordering: all 16 (i,j) MMAs of one split product issue before
// the next product touches the same accumulators (reuse distance 16 >= HMMA latency).
// smem: per stage 4 tiles (Ah,Al,Bh,Bl) of [128 rows x 32 bf16], row pitch 80B
// (16B x 5 -> conflict-free ldmatrix). Tile = 10240B; stage = 40960B; 2 stages.
#define TILE_BYTES   10240
#define STAGE_BYTES  40960
#define GEMM_SMEM    (2 * STAGE_BYTES)

__global__ void __launch_bounds__(256)
gemm_bf16mma(const __nv_bfloat16* __restrict__ Ah, const __nv_bfloat16* __restrict__ Al,
             const __nv_bfloat16* __restrict__ Bh, const __nv_bfloat16* __restrict__ Bl,
             float* __restrict__ C, int M, int N, int K,
             const float* __restrict__ bias, int epi)
{
    extern __shared__ __align__(128) char smem[];
    const uint32_t sbase = smem_u32(smem);
    const int tid  = threadIdx.x;
    const int lane = tid & 31;
    const int wid  = tid >> 5;
    const int warp_m = wid & 1;        // 2 x 64 rows
    const int warp_n = wid >> 1;       // 4 x 32 cols
    const int m0 = blockIdx.y * 128;
    const int n0 = blockIdx.x * 128;

    // ---- per-thread cp.async mapping: 8 chunks of 16B per stage ----
    const __nv_bfloat16* gsrc[8];
    uint32_t sdst[8];
#pragma unroll
    for (int i = 0; i < 8; i++) {
        int idx  = tid + 256 * i;      // 0..2047
        int tile = idx >> 9;           // 0:Ah 1:Al 2:Bh 3:Bl
        int w    = idx & 511;
        int row  = w >> 2;             // 0..127
        int c    = w & 3;              // 16B chunk in row
        const __nv_bfloat16* base =
            (tile == 0) ? Ah : (tile == 1) ? Al : (tile == 2) ? Bh : Bl;
        int grow = (tile < 2) ? (m0 + row) : (n0 + row);
        gsrc[i] = base + (size_t)grow * K + c * 8;
        sdst[i] = (uint32_t)(tile * TILE_BYTES + row * 80 + c * 16);
    }

    // ---- ldmatrix lane->address offsets ----
    const int rowA = lane & 15;
    const int colA = ((lane >> 4) & 1) * 16;
    const uint32_t offA = (uint32_t)((warp_m * 64 + rowA) * 80 + colA);
    const int rowB = ((lane >> 4) & 1) * 8 + (lane & 7);
    const int colB = ((lane >> 3) & 1) * 16;
    const uint32_t offB = (uint32_t)((warp_n * 32 + rowB) * 80 + colB);

    float acc[4][4][4];
#pragma unroll
    for (int i = 0; i < 4; i++)
#pragma unroll
        for (int j = 0; j < 4; j++)
#pragma unroll
            for (int q = 0; q < 4; q++) acc[i][j][q] = 0.0f;

    const int nk = K >> 5;             // K/32 chunks

    // ---- prologue: stage 0 ----
    {
        const uint32_t sb = sbase;
#pragma unroll
        for (int i = 0; i < 8; i++) cp16(sb + sdst[i], gsrc[i]);
        cp_commit();
    }

    for (int kt = 0; kt < nk; kt++) {
        const int cur = kt & 1;
        if (kt + 1 < nk) {
            const uint32_t sb = sbase + (cur ^ 1) * STAGE_BYTES;
            const int kofs = (kt + 1) << 5;
#pragma unroll
            for (int i = 0; i < 8; i++) cp16(sb + sdst[i], gsrc[i] + kofs);
            cp_commit();
            asm volatile("cp.async.wait_group 1;" ::: "memory");
        } else {
            asm volatile("cp.async.wait_group 0;" ::: "memory");
        }
        __syncthreads();

        const uint32_t sb = sbase + cur * STAGE_BYTES;
#pragma unroll
        for (int ks = 0; ks < 2; ks++) {
            uint32_t aH[4][4], aL[4][4], bH[4][2], bL[4][2], t4[4];
#pragma unroll
            for (int i = 0; i < 4; i++) {
                ldsm4(aH[i], sb + 0 * TILE_BYTES + offA + i * 1280 + ks * 32);
                ldsm4(aL[i], sb + 1 * TILE_BYTES + offA + i * 1280 + ks * 32);
            }
            ldsm4(t4, sb + 2 * TILE_BYTES + offB + 0 * 1280 + ks * 32);
            bH[0][0] = t4[0]; bH[0][1] = t4[1]; bH[1][0] = t4[2]; bH[1][1] = t4[3];
            ldsm4(t4, sb + 2 * TILE_BYTES + offB + 1 * 1280 + ks * 32);
            bH[2][0] = t4[0]; bH[2][1] = t4[1]; bH[3][0] = t4[2]; bH[3][1] = t4[3];
            ldsm4(t4, sb + 3 * TILE_BYTES + offB + 0 * 1280 + ks * 32);
            bL[0][0] = t4[0]; bL[0][1] = t4[1]; bL[1][0] = t4[2]; bL[1][1] = t4[3];
            ldsm4(t4, sb + 3 * TILE_BYTES + offB + 1 * 1280 + ks * 32);
            bL[2][0] = t4[0]; bL[2][1] = t4[1]; bL[3][0] = t4[2]; bL[3][1] = t4[3];

            // product-major: 16 independent accs between same-acc reuses
#pragma unroll
            for (int i = 0; i < 4; i++)
#pragma unroll
                for (int j = 0; j < 4; j++)
                    mma16816(acc[i][j], aH[i], bH[j]);
#pragma unroll
            for (int i = 0; i < 4; i++)
#pragma unroll
                for (int j = 0; j < 4; j++)
                    mma16816(acc[i][j], aH[i], bL[j]);
#pragma unroll
            for (int i = 0; i < 4; i++)
#pragma unroll
                for (int j = 0; j < 4; j++)
                    mma16816(acc[i][j], aL[i], bH[j]);
        }
        __syncthreads();
    }

    // ---- epilogue: registers -> gmem ----
#pragma unroll
    for (int i = 0; i < 4; i++) {
        const int m = m0 + warp_m * 64 + i * 16 + (lane >> 2);
#pragma unroll
        for (int j = 0; j < 4; j++) {
            const int n = n0 + warp_n * 32 + j * 8 + (lane & 3) * 2;
            float c0 = acc[i][j][0], c1 = acc[i][j][1];
            float c2 = acc[i][j][2], c3 = acc[i][j][3];
            if (epi == 1) {
                const float b0 = bias[n], b1 = bias[n + 1];
                c0 = softplus_f(c0 + b0); c1 = softplus_f(c1 + b1);
                c2 = softplus_f(c2 + b0); c3 = softplus_f(c3 + b1);
            }
            float2 v01; v01.x = c0; v01.y = c1;
            float2 v23; v23.x = c2; v23.y = c3;
            *(float2*)(C + (size_t)m * N + n)       = v01;
            *(float2*)(C + (size_t)(m + 8) * N + n) = v23;
        }
    }
}

// ---------------- depthwise causal conv1d + SiLU -> bf16 split ----------------
__global__ void conv_silu_kernel(const float* __restrict__ conv_w,
                                 const float* __restrict__ conv_b)
{
    int idx = blockIdx.x * blockDim.x + threadIdx.x;    // over ROWS*D_INNER
    if (idx >= ROWS * D_INNER) return;
    int d   = idx & (D_INNER - 1);
    int row = idx >> 11;                 // / D_INNER
    int t   = row & (SEQ - 1);
    int b   = row >> 11;                 // / SEQ

    float acc = conv_b[d];
#pragma unroll
    for (int j = 0; j < D_CONV; j++) {
        int tt = t - (D_CONV - 1) + j;
        if (tt >= 0)
            acc = fmaf(conv_w[d * D_CONV + j],
                       g_xz[(size_t)(b * SEQ + tt) * (2 * D_INNER) + d], acc);
    }
    float sig = 1.0f / (1.0f + __expf(-acc));
    float v = acc * sig;
    __nv_bfloat16 h = __float2bfloat16_rn(v);
    g_xah[idx] = h;
    g_xal[idx] = __float2bfloat16_rn(v - __bfloat162float(h));
}

// ---------------- selective scan + gating -> bf16 split ----------------
__global__ void __launch_bounds__(256)
scan_kernel(const float* __restrict__ A_log, const float* __restrict__ Dp)
{
    int g   = blockIdx.x * blockDim.x + threadIdx.x;
    int s   = g & (D_STATE - 1);
    int dch = g >> 4;                    // b*D_INNER + d
    int b   = dch >> 11;                 // / D_INNER
    int d   = dch & (D_INNER - 1);

    const float a   = -__expf(A_log[d * D_STATE + s]);
    const float dpv = Dp[d];

    const float* dt_ptr = g_dt + (size_t)(b * SEQ) * D_INNER + d;
    const __nv_bfloat16* xh_ptr = g_xah + (size_t)(b * SEQ) * D_INNER + d;
    const __nv_bfloat16* xl_ptr = g_xal + (size_t)(b * SEQ) * D_INNER + d;
    const float* z_ptr  = g_xz + (size_t)(b * SEQ) * (2 * D_INNER) + D_INNER + d;
    __nv_bfloat16* yh_ptr = g_ygh + (size_t)(b * SEQ) * D_INNER + d;
    __nv_bfloat16* yl_ptr = g_ygl + (size_t)(b * SEQ) * D_INNER + d;

    float h = 0.0f;
#pragma unroll 4
    for (int t = 0; t < SEQ; t++) {
        float dtv = dt_ptr[(size_t)t * D_INNER];
        float xv  = __bfloat162float(xh_ptr[(size_t)t * D_INNER]) +
                    __bfloat162float(xl_ptr[(size_t)t * D_INNER]);
        float e   = __expf(dtv * a);
        h = fmaf(e, h, dtv * xv);

        float y = h;
        y += __shfl_xor_sync(0xffffffffu, y, 1);
        y += __shfl_xor_sync(0xffffffffu, y, 2);
        y += __shfl_xor_sync(0xffffffffu, y, 4);
        y += __shfl_xor_sync(0xffffffffu, y, 8);

        if (s == 0) {
            float zv  = z_ptr[(size_t)t * (2 * D_INNER)];
            float sig = 1.0f / (1.0f + __expf(-zv));
            float yg  = (y + dpv * xv) * (zv * sig);
            __nv_bfloat16 hh = __float2bfloat16_rn(yg);
            yh_ptr[(size_t)t * D_INNER] = hh;
            yl_ptr[(size_t)t * D_INNER] = __float2bfloat16_rn(yg - __bfloat162float(hh));
        }
    }
}

// ---------------- launch ----------------
extern "C" void kernel_launch(void* const* d_in, const int* in_sizes, int n_in,
                              void* d_out, int out_size)
{
    const float* x      = (const float*)d_in[0];
    const float* W_in   = (const float*)d_in[1];
    const float* conv_w = (const float*)d_in[2];
    const float* conv_b = (const float*)d_in[3];
    const float* A_log  = (const float*)d_in[4];
    const float* Dp     = (const float*)d_in[5];
    const float* W_dt   = (const float*)d_in[6];
    const float* b_dt   = (const float*)d_in[7];
    const float* W_out  = (const float*)d_in[8];
    float* out = (float*)d_out;

    // allow >48KB dynamic smem (no-op after first call)
    cudaFuncSetAttribute(gemm_bf16mma, cudaFuncAttributeMaxDynamicSharedMemorySize,
                         GEMM_SMEM);

    float *p_xz, *p_dt;
    cudaGetSymbolAddress((void**)&p_xz, g_xz);
    cudaGetSymbolAddress((void**)&p_dt, g_dt);
    __nv_bfloat16 *p_xh, *p_xl, *p_wih, *p_wil, *p_wdh, *p_wdl, *p_woh, *p_wol;
    __nv_bfloat16 *p_xah, *p_xal, *p_ygh, *p_ygl;
    cudaGetSymbolAddress((void**)&p_xh,  g_xh);
    cudaGetSymbolAddress((void**)&p_xl,  g_xl);
    cudaGetSymbolAddress((void**)&p_wih, g_wih);
    cudaGetSymbolAddress((void**)&p_wil, g_wil);
    cudaGetSymbolAddress((void**)&p_wdh, g_wdh);
    cudaGetSymbolAddress((void**)&p_wdl, g_wdl);
    cudaGetSymbolAddress((void**)&p_woh, g_woh);
    cudaGetSymbolAddress((void**)&p_wol, g_wol);
    cudaGetSymbolAddress((void**)&p_xah, g_xah);
    cudaGetSymbolAddress((void**)&p_xal, g_xal);
    cudaGetSymbolAddress((void**)&p_ygh, g_ygh);
    cudaGetSymbolAddress((void**)&p_ygl, g_ygl);

    // splits of inputs/weights
    split_kernel<<<(ROWS * D_MODEL) / 1024, 256>>>(x, p_xh, p_xl, ROWS * D_MODEL);
    split_kernel<<<(2 * D_INNER * D_MODEL) / 1024, 256>>>(W_in, p_wih, p_wil, 2 * D_INNER * D_MODEL);
    split_kernel<<<(D_INNER * D_INNER) / 1024, 256>>>(W_dt, p_wdh, p_wdl, D_INNER * D_INNER);
    split_kernel<<<(D_MODEL * D_INNER) / 1024, 256>>>(W_out, p_woh, p_wol, D_MODEL * D_INNER);

    // G1: xz = x @ W_in^T   [4096,1024] x [4096,1024]^T -> [4096,4096]
    gemm_bf16mma<<<dim3((2 * D_INNER) / 128, ROWS / 128), 256, GEMM_SMEM>>>(
        p_xh, p_xl, p_wih, p_wil, p_xz, ROWS, 2 * D_INNER, D_MODEL, nullptr, 0);

    // conv + silu -> xact (bf16 split)
    conv_silu_kernel<<<(ROWS * D_INNER) / 256, 256>>>(conv_w, conv_b);

    // G2: dt = softplus(xact @ W_dt^T + b_dt)  [4096,2048]x[2048,2048]^T
    gemm_bf16mma<<<dim3(D_INNER / 128, ROWS / 128), 256, GEMM_SMEM>>>(
        p_xah, p_xal, p_wdh, p_wdl, p_dt, ROWS, D_INNER, D_INNER, b_dt, 1);

    // scan + gating -> yg (bf16 split)
    scan_kernel<<<(BATCH * D_INNER * D_STATE) / 256, 256>>>(A_log, Dp);

    // G3: out = yg @ W_out^T -> [4096,1024]
    gemm_bf16mma<<<dim3(D_MODEL / 128, ROWS / 128), 256, GEMM_SMEM>>>(
        p_ygh, p_ygl, p_woh, p_wol, out, ROWS, D_MODEL, D_INNER, nullptr, 0);
}

// round 9
// speedup vs baseline: 1.8856x; 1.3641x over previous
#include <cuda_runtime.h>
#include <cuda_fp16.h>
#include <cstdint>

// ---------------- problem constants ----------------
#define D_MODEL  1024
#define D_STATE  16
#define D_CONV   4
#define D_INNER  2048
#define BATCH    2
#define SEQ      2048
#define ROWS     (BATCH*SEQ)          // 4096

// ---------------- scratch (static __device__, no allocs) ----------------
__device__ float g_xz[ROWS * 2 * D_INNER];   // [4096,4096] x_proj | z (fp32)
__device__ float g_dt[ROWS * D_INNER];       // softplus(dt) (fp32)

// fp16 operands
__device__ __half g_xh[ROWS * D_MODEL];              // x in fp16
__device__ __half g_wi[2 * D_INNER * D_MODEL];       // W_in fp16
__device__ __half g_wd[D_INNER * D_INNER];           // W_dt fp16
__device__ __half g_wo[D_MODEL * D_INNER];           // W_out fp16
__device__ __half g_xa[ROWS * D_INNER];              // conv+silu output fp16
__device__ __half g_yg[ROWS * D_INNER];              // gated ssm output fp16

// ---------------- PTX helpers (baseline ISA only — no 'a' features) ----------------
__device__ __forceinline__ uint32_t smem_u32(const void* p) {
    uint32_t a;
    asm("{ .reg .u64 t; cvta.to.shared.u64 t, %1; cvt.u32.u64 %0, t; }" : "=r"(a) : "l"(p));
    return a;
}
__device__ __forceinline__ void cp16(uint32_t dst, const void* src) {
    asm volatile("cp.async.cg.shared.global [%0], [%1], 16;" :: "r"(dst), "l"(src));
}
__device__ __forceinline__ void cp_commit() {
    asm volatile("cp.async.commit_group;" ::: "memory");
}
__device__ __forceinline__ void ldsm4(uint32_t* r, uint32_t addr) {
    asm volatile("ldmatrix.sync.aligned.m8n8.x4.shared.b16 {%0,%1,%2,%3}, [%4];"
                 : "=r"(r[0]), "=r"(r[1]), "=r"(r[2]), "=r"(r[3]) : "r"(addr));
}
__device__ __forceinline__ void mma16816(float* c, const uint32_t* a, const uint32_t* b) {
    asm volatile("mma.sync.aligned.m16n8k16.row.col.f32.f16.f16.f32 "
                 "{%0,%1,%2,%3}, {%4,%5,%6,%7}, {%8,%9}, {%0,%1,%2,%3};"
                 : "+f"(c[0]), "+f"(c[1]), "+f"(c[2]), "+f"(c[3])
                 : "r"(a[0]), "r"(a[1]), "r"(a[2]), "r"(a[3]), "r"(b[0]), "r"(b[1]));
}

__device__ __forceinline__ float softplus_f(float v) {
    return fmaxf(v, 0.0f) + log1pf(__expf(-fabsf(v)));
}

// ---------------- convert kernel: fp32 -> fp16 ----------------
__global__ void tohalf_kernel(const float* __restrict__ in,
                              __half* __restrict__ out, int n)
{
    int i = (blockIdx.x * blockDim.x + threadIdx.x) * 4;
    if (i >= n) return;
    float4 v = *(const float4*)(in + i);
    __half2 p0 = __floats2half2_rn(v.x, v.y);
    __half2 p1 = __floats2half2_rn(v.z, v.w);
    *(__half2*)(out + i)     = p0;
    *(__half2*)(out + i + 2) = p1;
}

// ---------------- warp-MMA GEMM: C[M,N] = A[M,K] @ B[N,K]^T (fp16 in, fp32 acc) ----------------
// 128x128 CTA tile, BK=32, 8 warps (2x4 -> 64x32 per warp), single fp16 product.
// 2-stage cp.async pipeline. smem: per stage 2 tiles (A,B) of [128 rows x 32 halves],
// row pitch 80B (16Bx5 -> conflict-free ldmatrix). Tile = 10240B; stage = 20480B.
#define TILE_BYTES   10240
#define STAGE_BYTES  20480
#define GEMM_SMEM    (2 * STAGE_BYTES)

__global__ void __launch_bounds__(256)
gemm_f16mma(const __half* __restrict__ A, const __half* __restrict__ B,
            float* __restrict__ C, int M, int N, int K,
            const float* __restrict__ bias, int epi)
{
    extern __shared__ __align__(128) char smem[];
    const uint32_t sbase = smem_u32(smem);
    const int tid  = threadIdx.x;
    const int lane = tid & 31;
    const int wid  = tid >> 5;
    const int warp_m = wid & 1;        // 2 x 64 rows
    const int warp_n = wid >> 1;       // 4 x 32 cols
    const int m0 = blockIdx.y * 128;
    const int n0 = blockIdx.x * 128;

    // ---- per-thread cp.async mapping: 4 chunks of 16B per stage ----
    const __half* gsrc[4];
    uint32_t sdst[4];
#pragma unroll
    for (int i = 0; i < 4; i++) {
        int idx  = tid + 256 * i;      // 0..1023
        int tile = idx >> 9;           // 0:A 1:B
        int w    = idx & 511;
        int row  = w >> 2;             // 0..127
        int c    = w & 3;              // 16B chunk in row
        const __half* base = (tile == 0) ? A : B;
        int grow = (tile == 0) ? (m0 + row) : (n0 + row);
        gsrc[i] = base + (size_t)grow * K + c * 8;
        sdst[i] = (uint32_t)(tile * TILE_BYTES + row * 80 + c * 16);
    }

    // ---- ldmatrix lane->address offsets ----
    const int rowA = lane & 15;
    const int colA = ((lane >> 4) & 1) * 16;
    const uint32_t offA = (uint32_t)((warp_m * 64 + rowA) * 80 + colA);
    const int rowB = ((lane >> 4) & 1) * 8 + (lane & 7);
    const int colB = ((lane >> 3) & 1) * 16;
    const uint32_t offB = (uint32_t)((warp_n * 32 + rowB) * 80 + colB);

    float acc[4][4][4];
#pragma unroll
    for (int i = 0; i < 4; i++)
#pragma unroll
        for (int j = 0; j < 4; j++)
#pragma unroll
            for (int q = 0; q < 4; q++) acc[i][j][q] = 0.0f;

    const int nk = K >> 5;             // K/32 chunks

    // ---- prologue: stage 0 ----
    {
        const uint32_t sb = sbase;
#pragma unroll
        for (int i = 0; i < 4; i++) cp16(sb + sdst[i], gsrc[i]);
        cp_commit();
    }

    for (int kt = 0; kt < nk; kt++) {
        const int cur = kt & 1;
        if (kt + 1 < nk) {
            const uint32_t sb = sbase + (cur ^ 1) * STAGE_BYTES;
            const int kofs = (kt + 1) << 5;
#pragma unroll
            for (int i = 0; i < 4; i++) cp16(sb + sdst[i], gsrc[i] + kofs);
            cp_commit();
            asm volatile("cp.async.wait_group 1;" ::: "memory");
        } else {
            asm volatile("cp.async.wait_group 0;" ::: "memory");
        }
        __syncthreads();

        const uint32_t sb = sbase + cur * STAGE_BYTES;
#pragma unroll
        for (int ks = 0; ks < 2; ks++) {
            uint32_t a4[4][4], b4[4][2], t4[4];
#pragma unroll
            for (int i = 0; i < 4; i++)
                ldsm4(a4[i], sb + 0 * TILE_BYTES + offA + i * 1280 + ks * 32);
            ldsm4(t4, sb + 1 * TILE_BYTES + offB + 0 * 1280 + ks * 32);
            b4[0][0] = t4[0]; b4[0][1] = t4[1]; b4[1][0] = t4[2]; b4[1][1] = t4[3];
            ldsm4(t4, sb + 1 * TILE_BYTES + offB + 1 * 1280 + ks * 32);
            b4[2][0] = t4[0]; b4[2][1] = t4[1]; b4[3][0] = t4[2]; b4[3][1] = t4[3];

#pragma unroll
            for (int i = 0; i < 4; i++)
#pragma unroll
                for (int j = 0; j < 4; j++)
                    mma16816(acc[i][j], a4[i], b4[j]);
        }
        __syncthreads();
    }

    // ---- epilogue: registers -> gmem ----
#pragma unroll
    for (int i = 0; i < 4; i++) {
        const int m = m0 + warp_m * 64 + i * 16 + (lane >> 2);
#pragma unroll
        for (int j = 0; j < 4; j++) {
            const int n = n0 + warp_n * 32 + j * 8 + (lane & 3) * 2;
            float c0 = acc[i][j][0], c1 = acc[i][j][1];
            float c2 = acc[i][j][2], c3 = acc[i][j][3];
            if (epi == 1) {
                const float b0 = bias[n], b1 = bias[n + 1];
                c0 = softplus_f(c0 + b0); c1 = softplus_f(c1 + b1);
                c2 = softplus_f(c2 + b0); c3 = softplus_f(c3 + b1);
            }
            float2 v01; v01.x = c0; v01.y = c1;
            float2 v23; v23.x = c2; v23.y = c3;
            *(float2*)(C + (size_t)m * N + n)       = v01;
            *(float2*)(C + (size_t)(m + 8) * N + n) = v23;
        }
    }
}

// ---------------- depthwise causal conv1d + SiLU -> fp16 ----------------
__global__ void conv_silu_kernel(const float* __restrict__ conv_w,
                                 const float* __restrict__ conv_b)
{
    int idx = blockIdx.x * blockDim.x + threadIdx.x;    // over ROWS*D_INNER
    if (idx >= ROWS * D_INNER) return;
    int d   = idx & (D_INNER - 1);
    int row = idx >> 11;                 // / D_INNER
    int t   = row & (SEQ - 1);
    int b   = row >> 11;                 // / SEQ

    float acc = conv_b[d];
#pragma unroll
    for (int j = 0; j < D_CONV; j++) {
        int tt = t - (D_CONV - 1) + j;
        if (tt >= 0)
            acc = fmaf(conv_w[d * D_CONV + j],
                       g_xz[(size_t)(b * SEQ + tt) * (2 * D_INNER) + d], acc);
    }
    float sig = 1.0f / (1.0f + __expf(-acc));
    g_xa[idx] = __float2half_rn(acc * sig);
}

// ---------------- selective scan + gating -> fp16 ----------------
// one thread per (b, d, s): 65536 threads; lanes [16k..16k+15] share a channel
__global__ void __launch_bounds__(256)
scan_kernel(const float* __restrict__ A_log, const float* __restrict__ Dp)
{
    int g   = blockIdx.x * blockDim.x + threadIdx.x;
    int s   = g & (D_STATE - 1);
    int dch = g >> 4;                    // b*D_INNER + d
    int b   = dch >> 11;                 // / D_INNER
    int d   = dch & (D_INNER - 1);

    const float a   = -__expf(A_log[d * D_STATE + s]);
    const float dpv = Dp[d];

    const float* dt_ptr = g_dt + (size_t)(b * SEQ) * D_INNER + d;
    const __half* x_ptr = g_xa + (size_t)(b * SEQ) * D_INNER + d;
    const float* z_ptr  = g_xz + (size_t)(b * SEQ) * (2 * D_INNER) + D_INNER + d;
    __half* y_ptr       = g_yg + (size_t)(b * SEQ) * D_INNER + d;

    float h = 0.0f;
#pragma unroll 4
    for (int t = 0; t < SEQ; t++) {
        float dtv = dt_ptr[(size_t)t * D_INNER];
        float xv  = __half2float(x_ptr[(size_t)t * D_INNER]);
        float e   = __expf(dtv * a);
        h = fmaf(e, h, dtv * xv);

        float y = h;
        y += __shfl_xor_sync(0xffffffffu, y, 1);
        y += __shfl_xor_sync(0xffffffffu, y, 2);
        y += __shfl_xor_sync(0xffffffffu, y, 4);
        y += __shfl_xor_sync(0xffffffffu, y, 8);

        if (s == 0) {
            float zv  = z_ptr[(size_t)t * (2 * D_INNER)];
            float sig = 1.0f / (1.0f + __expf(-zv));
            y_ptr[(size_t)t * D_INNER] = __float2half_rn((y + dpv * xv) * (zv * sig));
        }
    }
}

// ---------------- launch ----------------
extern "C" void kernel_launch(void* const* d_in, const int* in_sizes, int n_in,
                              void* d_out, int out_size)
{
    const float* x      = (const float*)d_in[0];
    const float* W_in   = (const float*)d_in[1];
    const float* conv_w = (const float*)d_in[2];
    const float* conv_b = (const float*)d_in[3];
    const float* A_log  = (const float*)d_in[4];
    const float* Dp     = (const float*)d_in[5];
    const float* W_dt   = (const float*)d_in[6];
    const float* b_dt   = (const float*)d_in[7];
    const float* W_out  = (const float*)d_in[8];
    float* out = (float*)d_out;

    // allow >48KB dynamic smem path to be safe (no-op after first call)
    cudaFuncSetAttribute(gemm_f16mma, cudaFuncAttributeMaxDynamicSharedMemorySize,
                         GEMM_SMEM);

    float *p_xz, *p_dt;
    cudaGetSymbolAddress((void**)&p_xz, g_xz);
    cudaGetSymbolAddress((void**)&p_dt, g_dt);
    __half *p_xh, *p_wi, *p_wd, *p_wo, *p_xa, *p_yg;
    cudaGetSymbolAddress((void**)&p_xh, g_xh);
    cudaGetSymbolAddress((void**)&p_wi, g_wi);
    cudaGetSymbolAddress((void**)&p_wd, g_wd);
    cudaGetSymbolAddress((void**)&p_wo, g_wo);
    cudaGetSymbolAddress((void**)&p_xa, g_xa);
    cudaGetSymbolAddress((void**)&p_yg, g_yg);

    // fp32 -> fp16 conversions
    tohalf_kernel<<<(ROWS * D_MODEL) / 1024, 256>>>(x, p_xh, ROWS * D_MODEL);
    tohalf_kernel<<<(2 * D_INNER * D_MODEL) / 1024, 256>>>(W_in, p_wi, 2 * D_INNER * D_MODEL);
    tohalf_kernel<<<(D_INNER * D_INNER) / 1024, 256>>>(W_dt, p_wd, D_INNER * D_INNER);
    tohalf_kernel<<<(D_MODEL * D_INNER) / 1024, 256>>>(W_out, p_wo, D_MODEL * D_INNER);

    // G1: xz = x @ W_in^T   [4096,1024] x [4096,1024]^T -> [4096,4096]
    gemm_f16mma<<<dim3((2 * D_INNER) / 128, ROWS / 128), 256, GEMM_SMEM>>>(
        p_xh, p_wi, p_xz, ROWS, 2 * D_INNER, D_MODEL, nullptr, 0);

    // conv + silu -> xact (fp16)
    conv_silu_kernel<<<(ROWS * D_INNER) / 256, 256>>>(conv_w, conv_b);

    // G2: dt = softplus(xact @ W_dt^T + b_dt)  [4096,2048]x[2048,2048]^T
    gemm_f16mma<<<dim3(D_INNER / 128, ROWS / 128), 256, GEMM_SMEM>>>(
        p_xa, p_wd, p_dt, ROWS, D_INNER, D_INNER, b_dt, 1);

    // scan + gating -> yg (fp16)
    scan_kernel<<<(BATCH * D_INNER * D_STATE) / 256, 256>>>(A_log, Dp);

    // G3: out = yg @ W_out^T -> [4096,1024]
    gemm_f16mma<<<dim3(D_MODEL / 128, ROWS / 128), 256, GEMM_SMEM>>>(
        p_yg, p_wo, out, ROWS, D_MODEL, D_INNER, nullptr, 0);
}